// round 1
// baseline (speedup 1.0000x reference)
#include <cuda_runtime.h>
#include <cuda_bf16.h>

// EdgeConv: message MLP over edges + mean-aggregate + update MLP + residual.
// Inputs (metadata order): x(N,64) f32, edge_index(2,E) i32, edge_attr(E,16) f32,
//   W1(144,64), b1(64), W2(64,64), b2(64), Wu(128,64), bu(64) all f32.
// Output: (N,64) f32.

#define ND      64
#define EDIM    16
#define HID     64
#define MSGIN   144   // 2*ND + EDIM
#define TILE_E  64
#define TILE_N  64
#define MAXN    100000

// Scratch (device globals: no allocation allowed in kernel_launch)
__device__ float g_agg[(size_t)MAXN * HID];
__device__ float g_cnt[MAXN];

#define FMA16(ACC, AV, BV)                                                    \
  ACC[0][0] = fmaf(AV.x, BV.x, ACC[0][0]);                                    \
  ACC[0][1] = fmaf(AV.x, BV.y, ACC[0][1]);                                    \
  ACC[0][2] = fmaf(AV.x, BV.z, ACC[0][2]);                                    \
  ACC[0][3] = fmaf(AV.x, BV.w, ACC[0][3]);                                    \
  ACC[1][0] = fmaf(AV.y, BV.x, ACC[1][0]);                                    \
  ACC[1][1] = fmaf(AV.y, BV.y, ACC[1][1]);                                    \
  ACC[1][2] = fmaf(AV.y, BV.z, ACC[1][2]);                                    \
  ACC[1][3] = fmaf(AV.y, BV.w, ACC[1][3]);                                    \
  ACC[2][0] = fmaf(AV.z, BV.x, ACC[2][0]);                                    \
  ACC[2][1] = fmaf(AV.z, BV.y, ACC[2][1]);                                    \
  ACC[2][2] = fmaf(AV.z, BV.z, ACC[2][2]);                                    \
  ACC[2][3] = fmaf(AV.z, BV.w, ACC[2][3]);                                    \
  ACC[3][0] = fmaf(AV.w, BV.x, ACC[3][0]);                                    \
  ACC[3][1] = fmaf(AV.w, BV.y, ACC[3][1]);                                    \
  ACC[3][2] = fmaf(AV.w, BV.z, ACC[3][2]);                                    \
  ACC[3][3] = fmaf(AV.w, BV.w, ACC[3][3]);

// ---------------------------------------------------------------------------
// Zero the aggregation scratch (graph replays re-run this every launch).
// ---------------------------------------------------------------------------
__global__ void zero_kernel(int N) {
    long long i = (long long)blockIdx.x * blockDim.x + threadIdx.x;
    long long stride = (long long)gridDim.x * blockDim.x;
    float4* a4 = reinterpret_cast<float4*>(g_agg);
    long long n4 = (long long)N * (HID / 4);
    float4 z = make_float4(0.f, 0.f, 0.f, 0.f);
    for (long long j = i; j < n4; j += stride) a4[j] = z;
    for (long long j = i; j < N; j += stride) g_cnt[j] = 0.f;
}

// ---------------------------------------------------------------------------
// Edge kernel: per 64-edge tile, gather [x[src],x[dst],ea] -> SMEM (k-major),
// GEMM1 (144x64) + ReLU -> SMEM, GEMM2 (64x64), atomic scatter (msg + b2).
// Persistent grid-stride blocks; weights staged once per block.
// Shared: W1 9216 + W2 4096 + In 9216 + H 4096 + b1 64 + b2 64 floats + 64 int
// = 107264 bytes.
// ---------------------------------------------------------------------------
__global__ void __launch_bounds__(256, 2)
edge_kernel(const float* __restrict__ x, const int* __restrict__ eidx,
            const float* __restrict__ ea, const float* __restrict__ W1,
            const float* __restrict__ b1, const float* __restrict__ W2,
            const float* __restrict__ b2, int N, int E, int ntiles) {
    extern __shared__ float sm[];
    float* sW1 = sm;                       // [144][64]
    float* sW2 = sW1 + MSGIN * HID;        // [64][64]
    float* sIn = sW2 + HID * HID;          // [144][64]  (k-major, e minor)
    float* sH  = sIn + MSGIN * TILE_E;     // [64][64]
    float* sB1 = sH + HID * TILE_E;        // [64]
    float* sB2 = sB1 + HID;                // [64]
    int*   sDst = reinterpret_cast<int*>(sB2 + HID);  // [64]

    const int tid = threadIdx.x;
    for (int i = tid; i < MSGIN * HID; i += 256) sW1[i] = W1[i];
    for (int i = tid; i < HID * HID; i += 256)   sW2[i] = W2[i];
    if (tid < HID) { sB1[tid] = b1[tid]; sB2[tid] = b2[tid]; }
    __syncthreads();

    const int tx = tid & 15;      // edge-group (4 edges each)
    const int ty = tid >> 4;      // hidden-group (4 outputs each)
    const int q  = tid & 3;       // gather quarter
    const int eg = tid >> 2;      // gather edge slot (0..63)

    const int* __restrict__ srcp = eidx;
    const int* __restrict__ dstp = eidx + E;

    for (int tile = blockIdx.x; tile < ntiles; tile += gridDim.x) {
        const int e0 = tile * TILE_E;

        // ---- gather: 4 threads per edge ----
        {
            const int e = e0 + eg;
            if (e < E) {
                const int s = srcp[e];
                const int d = dstp[e];
                if (q == 0) sDst[eg] = d;
                const float4* xs = reinterpret_cast<const float4*>(x + (size_t)s * ND);
                const float4* xd = reinterpret_cast<const float4*>(x + (size_t)d * ND);
#pragma unroll
                for (int i = 0; i < 4; i++) {
                    const int f4 = q + 4 * i;
                    const int k  = f4 * 4;
                    float4 v = xs[f4];
                    sIn[(k + 0) * TILE_E + eg] = v.x;
                    sIn[(k + 1) * TILE_E + eg] = v.y;
                    sIn[(k + 2) * TILE_E + eg] = v.z;
                    sIn[(k + 3) * TILE_E + eg] = v.w;
                    float4 w = xd[f4];
                    sIn[(ND + k + 0) * TILE_E + eg] = w.x;
                    sIn[(ND + k + 1) * TILE_E + eg] = w.y;
                    sIn[(ND + k + 2) * TILE_E + eg] = w.z;
                    sIn[(ND + k + 3) * TILE_E + eg] = w.w;
                }
                float4 a = reinterpret_cast<const float4*>(ea + (size_t)e * EDIM)[q];
                const int k = 2 * ND + q * 4;
                sIn[(k + 0) * TILE_E + eg] = a.x;
                sIn[(k + 1) * TILE_E + eg] = a.y;
                sIn[(k + 2) * TILE_E + eg] = a.z;
                sIn[(k + 3) * TILE_E + eg] = a.w;
            }
        }
        __syncthreads();

        // ---- GEMM1: (64 edges x 144) @ (144 x 64) ----
        float acc[4][4];
#pragma unroll
        for (int a = 0; a < 4; a++)
#pragma unroll
            for (int b = 0; b < 4; b++) acc[a][b] = 0.f;

#pragma unroll 8
        for (int k = 0; k < MSGIN; k++) {
            float4 av = *reinterpret_cast<const float4*>(&sIn[k * TILE_E + tx * 4]);
            float4 bv = *reinterpret_cast<const float4*>(&sW1[k * HID + ty * 4]);
            FMA16(acc, av, bv)
        }

        // bias + relu -> sH[j][e]
#pragma unroll
        for (int ji = 0; ji < 4; ji++) {
            const float bb = sB1[ty * 4 + ji];
#pragma unroll
            for (int ei = 0; ei < 4; ei++) {
                float v = acc[ei][ji] + bb;
                sH[(ty * 4 + ji) * TILE_E + tx * 4 + ei] = v > 0.f ? v : 0.f;
            }
        }
        __syncthreads();

        // ---- GEMM2: (64 edges x 64) @ (64 x 64) ----
        float acc2[4][4];
#pragma unroll
        for (int a = 0; a < 4; a++)
#pragma unroll
            for (int b = 0; b < 4; b++) acc2[a][b] = 0.f;

#pragma unroll 8
        for (int k = 0; k < HID; k++) {
            float4 av = *reinterpret_cast<const float4*>(&sH[k * TILE_E + tx * 4]);
            float4 bv = *reinterpret_cast<const float4*>(&sW2[k * HID + ty * 4]);
            FMA16(acc2, av, bv)
        }

        // ---- scatter: message (+b2) atomics into g_agg; count atomics ----
#pragma unroll
        for (int ei = 0; ei < 4; ei++) {
            const int e = e0 + tx * 4 + ei;
            if (e < E) {
                const int d = sDst[tx * 4 + ei];
                float* base = g_agg + (size_t)d * HID + ty * 4;
#pragma unroll
                for (int ji = 0; ji < 4; ji++)
                    atomicAdd(base + ji, acc2[ei][ji] + sB2[ty * 4 + ji]);
            }
        }
        if (ty == 0) {
#pragma unroll
            for (int ei = 0; ei < 4; ei++) {
                const int e = e0 + tx * 4 + ei;
                if (e < E) atomicAdd(&g_cnt[sDst[tx * 4 + ei]], 1.0f);
            }
        }
        __syncthreads();
    }
}

// ---------------------------------------------------------------------------
// Node kernel: normalize aggregate, update MLP, ReLU, residual.
// Mean-normalization folded as post-scale: acc = accX + inv(cnt)*accAgg.
// Shared: Wu 8192 + In 8192 + bu 64 + inv 64 floats = 66048 bytes.
// ---------------------------------------------------------------------------
__global__ void __launch_bounds__(256, 3)
node_kernel(const float* __restrict__ x, const float* __restrict__ Wu,
            const float* __restrict__ bu, float* __restrict__ out,
            int N, int ntiles) {
    extern __shared__ float sm[];
    float* sWu  = sm;                      // [128][64]
    float* sIn  = sWu + 2 * ND * HID;      // [128][64]  (k-major, node minor)
    float* sBu  = sIn + 2 * ND * TILE_N;   // [64]
    float* sInv = sBu + HID;               // [64]

    const int tid = threadIdx.x;
    for (int i = tid; i < 2 * ND * HID; i += 256) sWu[i] = Wu[i];
    if (tid < HID) sBu[tid] = bu[tid];
    __syncthreads();

    const int tx = tid & 15;
    const int ty = tid >> 4;
    const int q  = tid & 3;
    const int ng = tid >> 2;

    for (int tile = blockIdx.x; tile < ntiles; tile += gridDim.x) {
        const int n0 = tile * TILE_N;
        {
            const int n = n0 + ng;
            if (n < N) {
                if (q == 0) sInv[ng] = 1.0f / (g_cnt[n] + 1e-6f);
                const float4* xr = reinterpret_cast<const float4*>(x + (size_t)n * ND);
                const float4* ar = reinterpret_cast<const float4*>(g_agg + (size_t)n * HID);
#pragma unroll
                for (int i = 0; i < 4; i++) {
                    const int f4 = q + 4 * i;
                    const int k  = f4 * 4;
                    float4 v = xr[f4];
                    sIn[(k + 0) * TILE_N + ng] = v.x;
                    sIn[(k + 1) * TILE_N + ng] = v.y;
                    sIn[(k + 2) * TILE_N + ng] = v.z;
                    sIn[(k + 3) * TILE_N + ng] = v.w;
                    float4 w = ar[f4];
                    sIn[(ND + k + 0) * TILE_N + ng] = w.x;
                    sIn[(ND + k + 1) * TILE_N + ng] = w.y;
                    sIn[(ND + k + 2) * TILE_N + ng] = w.z;
                    sIn[(ND + k + 3) * TILE_N + ng] = w.w;
                }
            }
        }
        __syncthreads();

        float accX[4][4], accA[4][4];
#pragma unroll
        for (int a = 0; a < 4; a++)
#pragma unroll
            for (int b = 0; b < 4; b++) { accX[a][b] = 0.f; accA[a][b] = 0.f; }

#pragma unroll 8
        for (int k = 0; k < ND; k++) {
            float4 av = *reinterpret_cast<const float4*>(&sIn[k * TILE_N + tx * 4]);
            float4 bv = *reinterpret_cast<const float4*>(&sWu[k * HID + ty * 4]);
            FMA16(accX, av, bv)
        }
#pragma unroll 8
        for (int k = ND; k < 2 * ND; k++) {
            float4 av = *reinterpret_cast<const float4*>(&sIn[k * TILE_N + tx * 4]);
            float4 bv = *reinterpret_cast<const float4*>(&sWu[k * HID + ty * 4]);
            FMA16(accA, av, bv)
        }

#pragma unroll
        for (int ei = 0; ei < 4; ei++) {
            const int n = n0 + tx * 4 + ei;
            if (n < N) {
                const float inv = sInv[tx * 4 + ei];
                float4 o;
                float r;
                r = accX[ei][0] + inv * accA[ei][0] + sBu[ty * 4 + 0];
                o.x = sIn[(ty * 4 + 0) * TILE_N + tx * 4 + ei] + (r > 0.f ? r : 0.f);
                r = accX[ei][1] + inv * accA[ei][1] + sBu[ty * 4 + 1];
                o.y = sIn[(ty * 4 + 1) * TILE_N + tx * 4 + ei] + (r > 0.f ? r : 0.f);
                r = accX[ei][2] + inv * accA[ei][2] + sBu[ty * 4 + 2];
                o.z = sIn[(ty * 4 + 2) * TILE_N + tx * 4 + ei] + (r > 0.f ? r : 0.f);
                r = accX[ei][3] + inv * accA[ei][3] + sBu[ty * 4 + 3];
                o.w = sIn[(ty * 4 + 3) * TILE_N + tx * 4 + ei] + (r > 0.f ? r : 0.f);
                *reinterpret_cast<float4*>(out + (size_t)n * HID + ty * 4) = o;
            }
        }
        __syncthreads();
    }
}

// ---------------------------------------------------------------------------
extern "C" void kernel_launch(void* const* d_in, const int* in_sizes, int n_in,
                              void* d_out, int out_size) {
    const float* x   = (const float*)d_in[0];
    const int*   ei  = (const int*)d_in[1];
    const float* ea  = (const float*)d_in[2];
    const float* W1  = (const float*)d_in[3];
    const float* b1  = (const float*)d_in[4];
    const float* W2  = (const float*)d_in[5];
    const float* b2  = (const float*)d_in[6];
    const float* Wu  = (const float*)d_in[7];
    const float* bu  = (const float*)d_in[8];
    float* out = (float*)d_out;

    const int N = in_sizes[0] / ND;     // 100000
    const int E = in_sizes[2] / EDIM;   // 1600000

    const int smem_edge = (MSGIN * HID + HID * HID + MSGIN * TILE_E +
                           HID * TILE_E + 2 * HID) * 4 + TILE_E * 4;
    const int smem_node = (2 * ND * HID + 2 * ND * TILE_N + 2 * HID) * 4;

    cudaFuncSetAttribute(edge_kernel, cudaFuncAttributeMaxDynamicSharedMemorySize,
                         smem_edge);
    cudaFuncSetAttribute(node_kernel, cudaFuncAttributeMaxDynamicSharedMemorySize,
                         smem_node);

    const int etiles = (E + TILE_E - 1) / TILE_E;
    const int ntiles = (N + TILE_N - 1) / TILE_N;

    zero_kernel<<<2048, 256>>>(N);
    edge_kernel<<<304, 256, smem_edge>>>(x, ei, ea, W1, b1, W2, b2, N, E, etiles);
    node_kernel<<<456, 256, smem_node>>>(x, Wu, bu, out, N, ntiles);
}

// round 2
// speedup vs baseline: 1.5434x; 1.5434x over previous
#include <cuda_runtime.h>
#include <cuda_bf16.h>
#include <mma.h>

using namespace nvcuda;

// EdgeConv: message MLP over edges + mean-aggregate + update MLP + residual.
// Inputs: x(N,64) f32, edge_index(2,E) i32, edge_attr(E,16) f32,
//   W1(144,64), b1(64), W2(64,64), b2(64), Wu(128,64), bu(64) f32.
// Output: (N,64) f32.

#define ND      64
#define EDIM    16
#define HID     64
#define MSGIN   144   // 2*ND + EDIM
#define TILE_N  64
#define MAXN    100000

#define LDIN    152   // 144 + 8 pad
#define LDW     72    // 64 + 8 pad
#define LDH     72

// Scratch (device globals: no allocation allowed)
__device__ float g_agg[(size_t)MAXN * HID];
__device__ float g_cnt[MAXN];

// ---------------------------------------------------------------------------
__global__ void zero_kernel(int N) {
    long long i = (long long)blockIdx.x * blockDim.x + threadIdx.x;
    long long stride = (long long)gridDim.x * blockDim.x;
    float4* a4 = reinterpret_cast<float4*>(g_agg);
    long long n4 = (long long)N * (HID / 4);
    float4 z = make_float4(0.f, 0.f, 0.f, 0.f);
    for (long long j = i; j < n4; j += stride) a4[j] = z;
    for (long long j = i; j < N; j += stride) g_cnt[j] = 0.f;
}

// ---------------------------------------------------------------------------
// Edge kernel (tf32 WMMA). 256 threads = 8 warps; each warp independently
// processes 16-edge tiles: gather -> GEMM1(K=144)+ReLU -> GEMM2(K=64) ->
// float4-atomic scatter. No block syncs in the main loop.
// SMEM: W1[144][72] W2[64][72] bias tiles 2x[16][72] In[128][152] H[128][72]
//       + dst[128] = ~184 KB -> 1 CTA/SM.
// ---------------------------------------------------------------------------
__global__ void __launch_bounds__(256, 1)
edge_kernel(const float* __restrict__ x, const int* __restrict__ eidx,
            const float* __restrict__ ea, const float* __restrict__ W1,
            const float* __restrict__ b1, const float* __restrict__ W2,
            const float* __restrict__ b2, int E, int nwt) {
    extern __shared__ __align__(32) float sm[];
    float* sW1  = sm;                       // 144*72
    float* sW2  = sW1 + MSGIN * LDW;        // 64*72
    float* sIn  = sW2 + HID * LDW;          // 128*152
    float* sH   = sIn + 128 * LDIN;         // 128*72
    float* sB1T = sH + 128 * LDH;           // 16*72 (rows replicated)
    float* sB2T = sB1T + 16 * LDW;          // 16*72
    int*   sDst = reinterpret_cast<int*>(sB2T + 16 * LDW);  // 128

    const int tid = threadIdx.x;

    // Stage weights (tf32-converted) + bias tiles
    for (int i = tid; i < MSGIN * HID; i += 256) {
        int k = i >> 6, n = i & 63;
        sW1[k * LDW + n] = wmma::__float_to_tf32(W1[i]);
    }
    for (int i = tid; i < HID * HID; i += 256) {
        int k = i >> 6, n = i & 63;
        sW2[k * LDW + n] = wmma::__float_to_tf32(W2[i]);
    }
    for (int i = tid; i < 16 * HID; i += 256) {
        int r = i >> 6, c = i & 63;
        sB1T[r * LDW + c] = b1[c];
        sB2T[r * LDW + c] = b2[c];
    }
    __syncthreads();

    const int wid  = tid >> 5;
    const int lane = tid & 31;
    const int r0   = wid * 16;            // this warp's SMEM row base
    const int gw   = blockIdx.x * 8 + wid;
    const int gstride = gridDim.x * 8;

    const int* __restrict__ srcp = eidx;
    const int* __restrict__ dstp = eidx + E;

    float* myIn = sIn + r0 * LDIN;
    float* myH  = sH + r0 * LDH;
    int*   myDst = sDst + r0;

    for (int t = gw; t < nwt; t += gstride) {
        const int e0 = t * 16;

        // ---- gather: 2 lanes per edge ----
        {
            const int row  = lane >> 1;
            const int half = lane & 1;
            const int e = e0 + row;
            float* rp = myIn + row * LDIN;
            if (e < E) {
                const int s = srcp[e];
                const int d = dstp[e];
                if (half == 0) myDst[row] = d;
                const float4* xs = reinterpret_cast<const float4*>(x + (size_t)s * ND) + half * 8;
                const float4* xd = reinterpret_cast<const float4*>(x + (size_t)d * ND) + half * 8;
                float4* w1p = reinterpret_cast<float4*>(rp) + half * 8;
                float4* w2p = reinterpret_cast<float4*>(rp + ND) + half * 8;
#pragma unroll
                for (int i = 0; i < 8; i++) {
                    float4 v = xs[i];
                    v.x = wmma::__float_to_tf32(v.x); v.y = wmma::__float_to_tf32(v.y);
                    v.z = wmma::__float_to_tf32(v.z); v.w = wmma::__float_to_tf32(v.w);
                    w1p[i] = v;
                    float4 u = xd[i];
                    u.x = wmma::__float_to_tf32(u.x); u.y = wmma::__float_to_tf32(u.y);
                    u.z = wmma::__float_to_tf32(u.z); u.w = wmma::__float_to_tf32(u.w);
                    w2p[i] = u;
                }
                const float4* ap = reinterpret_cast<const float4*>(ea + (size_t)e * EDIM) + half * 2;
                float4* w3p = reinterpret_cast<float4*>(rp + 2 * ND) + half * 2;
#pragma unroll
                for (int i = 0; i < 2; i++) {
                    float4 a = ap[i];
                    a.x = wmma::__float_to_tf32(a.x); a.y = wmma::__float_to_tf32(a.y);
                    a.z = wmma::__float_to_tf32(a.z); a.w = wmma::__float_to_tf32(a.w);
                    w3p[i] = a;
                }
            } else {
                float4 z = make_float4(0.f, 0.f, 0.f, 0.f);
                float4* zp = reinterpret_cast<float4*>(rp) + half * 19;
#pragma unroll
                for (int i = 0; i < 19; i++) zp[i] = z;
                if (half == 0) myDst[row] = 0;
            }
        }
        __syncwarp();

        // ---- GEMM1: (16 x 144) @ (144 x 64), bias preloaded in C ----
        wmma::fragment<wmma::accumulator, 16, 16, 8, float> c[4];
        wmma::fragment<wmma::matrix_a, 16, 16, 8, wmma::precision::tf32, wmma::row_major> af;
        wmma::fragment<wmma::matrix_b, 16, 16, 8, wmma::precision::tf32, wmma::row_major> bf;
#pragma unroll
        for (int j = 0; j < 4; j++)
            wmma::load_matrix_sync(c[j], sB1T + j * 16, LDW, wmma::mem_row_major);
#pragma unroll
        for (int k = 0; k < MSGIN / 8; k++) {
            wmma::load_matrix_sync(af, myIn + k * 8, LDIN);
#pragma unroll
            for (int j = 0; j < 4; j++) {
                wmma::load_matrix_sync(bf, sW1 + (k * 8) * LDW + j * 16, LDW);
                wmma::mma_sync(c[j], af, bf, c[j]);
            }
        }
        // ReLU + tf32 -> sH
#pragma unroll
        for (int j = 0; j < 4; j++) {
#pragma unroll
            for (int i = 0; i < c[j].num_elements; i++)
                c[j].x[i] = wmma::__float_to_tf32(fmaxf(c[j].x[i], 0.f));
            wmma::store_matrix_sync(myH + j * 16, c[j], LDH, wmma::mem_row_major);
        }
        __syncwarp();

        // ---- GEMM2: (16 x 64) @ (64 x 64), b2 preloaded in C ----
#pragma unroll
        for (int j = 0; j < 4; j++)
            wmma::load_matrix_sync(c[j], sB2T + j * 16, LDW, wmma::mem_row_major);
#pragma unroll
        for (int k = 0; k < HID / 8; k++) {
            wmma::load_matrix_sync(af, myH + k * 8, LDH);
#pragma unroll
            for (int j = 0; j < 4; j++) {
                wmma::load_matrix_sync(bf, sW2 + (k * 8) * LDW + j * 16, LDW);
                wmma::mma_sync(c[j], af, bf, c[j]);
            }
        }
        // messages -> sIn (reuse), then float4-atomic scatter
#pragma unroll
        for (int j = 0; j < 4; j++)
            wmma::store_matrix_sync(myIn + j * 16, c[j], LDIN, wmma::mem_row_major);
        __syncwarp();

#pragma unroll
        for (int i = 0; i < 8; i++) {
            const int idx = lane + 32 * i;     // 0..255 = 16 edges x 16 float4
            const int el  = idx >> 4;
            const int c4  = idx & 15;
            const int e = e0 + el;
            if (e < E) {
                const int d = myDst[el];
                float4 v = *reinterpret_cast<float4*>(myIn + el * LDIN + c4 * 4);
                atomicAdd(reinterpret_cast<float4*>(g_agg + (size_t)d * HID + c4 * 4), v);
            }
        }
        if (lane < 16 && e0 + lane < E)
            atomicAdd(&g_cnt[myDst[lane]], 1.0f);
        __syncwarp();
    }
}

// ---------------------------------------------------------------------------
// Node kernel: fp32 (exact), unchanged structure from R1.
// ---------------------------------------------------------------------------
#define FMA16(ACC, AV, BV)                                                    \
  ACC[0][0] = fmaf(AV.x, BV.x, ACC[0][0]);                                    \
  ACC[0][1] = fmaf(AV.x, BV.y, ACC[0][1]);                                    \
  ACC[0][2] = fmaf(AV.x, BV.z, ACC[0][2]);                                    \
  ACC[0][3] = fmaf(AV.x, BV.w, ACC[0][3]);                                    \
  ACC[1][0] = fmaf(AV.y, BV.x, ACC[1][0]);                                    \
  ACC[1][1] = fmaf(AV.y, BV.y, ACC[1][1]);                                    \
  ACC[1][2] = fmaf(AV.y, BV.z, ACC[1][2]);                                    \
  ACC[1][3] = fmaf(AV.y, BV.w, ACC[1][3]);                                    \
  ACC[2][0] = fmaf(AV.z, BV.x, ACC[2][0]);                                    \
  ACC[2][1] = fmaf(AV.z, BV.y, ACC[2][1]);                                    \
  ACC[2][2] = fmaf(AV.z, BV.z, ACC[2][2]);                                    \
  ACC[2][3] = fmaf(AV.z, BV.w, ACC[2][3]);                                    \
  ACC[3][0] = fmaf(AV.w, BV.x, ACC[3][0]);                                    \
  ACC[3][1] = fmaf(AV.w, BV.y, ACC[3][1]);                                    \
  ACC[3][2] = fmaf(AV.w, BV.z, ACC[3][2]);                                    \
  ACC[3][3] = fmaf(AV.w, BV.w, ACC[3][3]);

__global__ void __launch_bounds__(256, 3)
node_kernel(const float* __restrict__ x, const float* __restrict__ Wu,
            const float* __restrict__ bu, float* __restrict__ out,
            int N, int ntiles) {
    extern __shared__ float smn[];
    float* sWu  = smn;                     // [128][64]
    float* sIn  = sWu + 2 * ND * HID;      // [128][64]  (k-major, node minor)
    float* sBu  = sIn + 2 * ND * TILE_N;   // [64]
    float* sInv = sBu + HID;               // [64]

    const int tid = threadIdx.x;
    for (int i = tid; i < 2 * ND * HID; i += 256) sWu[i] = Wu[i];
    if (tid < HID) sBu[tid] = bu[tid];
    __syncthreads();

    const int tx = tid & 15;
    const int ty = tid >> 4;
    const int q  = tid & 3;
    const int ng = tid >> 2;

    for (int tile = blockIdx.x; tile < ntiles; tile += gridDim.x) {
        const int n0 = tile * TILE_N;
        {
            const int n = n0 + ng;
            if (n < N) {
                if (q == 0) sInv[ng] = 1.0f / (g_cnt[n] + 1e-6f);
                const float4* xr = reinterpret_cast<const float4*>(x + (size_t)n * ND);
                const float4* ar = reinterpret_cast<const float4*>(g_agg + (size_t)n * HID);
#pragma unroll
                for (int i = 0; i < 4; i++) {
                    const int f4 = q + 4 * i;
                    const int k  = f4 * 4;
                    float4 v = xr[f4];
                    sIn[(k + 0) * TILE_N + ng] = v.x;
                    sIn[(k + 1) * TILE_N + ng] = v.y;
                    sIn[(k + 2) * TILE_N + ng] = v.z;
                    sIn[(k + 3) * TILE_N + ng] = v.w;
                    float4 w = ar[f4];
                    sIn[(ND + k + 0) * TILE_N + ng] = w.x;
                    sIn[(ND + k + 1) * TILE_N + ng] = w.y;
                    sIn[(ND + k + 2) * TILE_N + ng] = w.z;
                    sIn[(ND + k + 3) * TILE_N + ng] = w.w;
                }
            }
        }
        __syncthreads();

        float accX[4][4], accA[4][4];
#pragma unroll
        for (int a = 0; a < 4; a++)
#pragma unroll
            for (int b = 0; b < 4; b++) { accX[a][b] = 0.f; accA[a][b] = 0.f; }

#pragma unroll 8
        for (int k = 0; k < ND; k++) {
            float4 av = *reinterpret_cast<const float4*>(&sIn[k * TILE_N + tx * 4]);
            float4 bv = *reinterpret_cast<const float4*>(&sWu[k * HID + ty * 4]);
            FMA16(accX, av, bv)
        }
#pragma unroll 8
        for (int k = ND; k < 2 * ND; k++) {
            float4 av = *reinterpret_cast<const float4*>(&sIn[k * TILE_N + tx * 4]);
            float4 bv = *reinterpret_cast<const float4*>(&sWu[k * HID + ty * 4]);
            FMA16(accA, av, bv)
        }

#pragma unroll
        for (int ei = 0; ei < 4; ei++) {
            const int n = n0 + tx * 4 + ei;
            if (n < N) {
                const float inv = sInv[tx * 4 + ei];
                float4 o;
                float r;
                r = accX[ei][0] + inv * accA[ei][0] + sBu[ty * 4 + 0];
                o.x = sIn[(ty * 4 + 0) * TILE_N + tx * 4 + ei] + (r > 0.f ? r : 0.f);
                r = accX[ei][1] + inv * accA[ei][1] + sBu[ty * 4 + 1];
                o.y = sIn[(ty * 4 + 1) * TILE_N + tx * 4 + ei] + (r > 0.f ? r : 0.f);
                r = accX[ei][2] + inv * accA[ei][2] + sBu[ty * 4 + 2];
                o.z = sIn[(ty * 4 + 2) * TILE_N + tx * 4 + ei] + (r > 0.f ? r : 0.f);
                r = accX[ei][3] + inv * accA[ei][3] + sBu[ty * 4 + 3];
                o.w = sIn[(ty * 4 + 3) * TILE_N + tx * 4 + ei] + (r > 0.f ? r : 0.f);
                *reinterpret_cast<float4*>(out + (size_t)n * HID + ty * 4) = o;
            }
        }
        __syncthreads();
    }
}

// ---------------------------------------------------------------------------
extern "C" void kernel_launch(void* const* d_in, const int* in_sizes, int n_in,
                              void* d_out, int out_size) {
    const float* x   = (const float*)d_in[0];
    const int*   ei  = (const int*)d_in[1];
    const float* ea  = (const float*)d_in[2];
    const float* W1  = (const float*)d_in[3];
    const float* b1  = (const float*)d_in[4];
    const float* W2  = (const float*)d_in[5];
    const float* b2  = (const float*)d_in[6];
    const float* Wu  = (const float*)d_in[7];
    const float* bu  = (const float*)d_in[8];
    float* out = (float*)d_out;

    const int N = in_sizes[0] / ND;     // 100000
    const int E = in_sizes[2] / EDIM;   // 1600000

    const int smem_edge = (MSGIN * LDW + HID * LDW + 128 * LDIN + 128 * LDH +
                           2 * 16 * LDW) * 4 + 128 * 4;
    const int smem_node = (2 * ND * HID + 2 * ND * TILE_N + 2 * HID) * 4;

    cudaFuncSetAttribute(edge_kernel, cudaFuncAttributeMaxDynamicSharedMemorySize,
                         smem_edge);
    cudaFuncSetAttribute(node_kernel, cudaFuncAttributeMaxDynamicSharedMemorySize,
                         smem_node);

    const int nwt = (E + 15) / 16;                 // 16-edge warp tiles
    const int ntiles = (N + TILE_N - 1) / TILE_N;

    zero_kernel<<<2048, 256>>>(N);
    edge_kernel<<<148, 256, smem_edge>>>(x, ei, ea, W1, b1, W2, b2, E, nwt);
    node_kernel<<<456, 256, smem_node>>>(x, Wu, bu, out, N, ntiles);
}

// round 3
// speedup vs baseline: 2.6684x; 1.7290x over previous
#include <cuda_runtime.h>
#include <cuda_bf16.h>
#include <mma.h>

using namespace nvcuda;

// EdgeConv: message MLP over edges + mean-aggregate + update MLP + residual.
// Inputs: x(N,64) f32, edge_index(2,E) i32, edge_attr(E,16) f32,
//   W1(144,64), b1(64), W2(64,64), b2(64), Wu(128,64), bu(64) f32.
// Output: (N,64) f32.

#define ND      64
#define EDIM    16
#define HID     64
#define MSGIN   144   // 2*ND + EDIM
#define TILE_N  64
#define MAXN    100000

// bf16 SMEM strides (elements). Chosen so 16B-phase accesses are bank-conflict
// free: row stride in 32-bit words ≡ {84, 44} -> 8 consecutive lanes hit
// distinct banks.
#define LDIN_H  168   // 336B rows for In (144 bf16 + pad)
#define LDW_H   88    // 176B rows for weights / H
#define LDSC_F  84    // 336B rows for f32 scratch (aliases In)
#define LDB_F   80    // bias tile f32

// Scratch (device globals: no allocation allowed)
__device__ float g_agg[(size_t)MAXN * HID];
__device__ float g_cnt[MAXN];

// ---------------------------------------------------------------------------
__global__ void zero_kernel(int N) {
    long long i = (long long)blockIdx.x * blockDim.x + threadIdx.x;
    long long stride = (long long)gridDim.x * blockDim.x;
    float4* a4 = reinterpret_cast<float4*>(g_agg);
    long long n4 = (long long)N * (HID / 4);
    float4 z = make_float4(0.f, 0.f, 0.f, 0.f);
    for (long long j = i; j < n4; j += stride) a4[j] = z;
    for (long long j = i; j < N; j += stride) g_cnt[j] = 0.f;
}

// ---------------------------------------------------------------------------
// Edge kernel (bf16 WMMA 16x16x16). 8 warps/CTA; each warp owns independent
// 32-edge tiles: gather(f32->bf16) -> GEMM1(K=144)+ReLU -> GEMM2(K=64,
// register-resident weights) -> float4-atomic scatter. No block syncs in loop.
// ---------------------------------------------------------------------------
__global__ void __launch_bounds__(256, 1)
edge_kernel(const float* __restrict__ x, const int* __restrict__ eidx,
            const float* __restrict__ ea, const float* __restrict__ W1,
            const float* __restrict__ b1, const float* __restrict__ W2,
            int E, int nwt) {
    extern __shared__ __align__(16) char smraw[];
    __nv_bfloat16* sW1h = reinterpret_cast<__nv_bfloat16*>(smraw);             // 144*88
    __nv_bfloat16* sW2h = sW1h + MSGIN * LDW_H;                                // 64*88
    float*         sB1T = reinterpret_cast<float*>(sW2h + HID * LDW_H);        // 16*80
    __nv_bfloat16* sInH = reinterpret_cast<__nv_bfloat16*>(sB1T + 16 * LDB_F); // 256*168
    __nv_bfloat16* sHh  = sInH + 256 * LDIN_H;                                 // 256*88
    int*           sDst = reinterpret_cast<int*>(sHh + 256 * LDW_H);           // 256

    const int tid = threadIdx.x;

    // Stage weights (bf16) + replicated b1 tile
    for (int i = tid; i < MSGIN * HID; i += 256) {
        int k = i >> 6, n = i & 63;
        sW1h[k * LDW_H + n] = __float2bfloat16_rn(W1[i]);
    }
    for (int i = tid; i < HID * HID; i += 256) {
        int k = i >> 6, n = i & 63;
        sW2h[k * LDW_H + n] = __float2bfloat16_rn(W2[i]);
    }
    for (int i = tid; i < 16 * HID; i += 256) {
        int r = i >> 6, c = i & 63;
        sB1T[r * LDB_F + c] = b1[c];
    }
    __syncthreads();

    const int wid  = tid >> 5;
    const int lane = tid & 31;
    const int r0   = wid * 32;
    const int gw   = blockIdx.x * 8 + wid;
    const int gstride = gridDim.x * 8;

    const int* __restrict__ srcp = eidx;
    const int* __restrict__ dstp = eidx + E;

    __nv_bfloat16* myInH = sInH + r0 * LDIN_H;
    float*         myScr = reinterpret_cast<float*>(myInH);   // aliases In
    __nv_bfloat16* myHh  = sHh + r0 * LDW_H;
    int*           myDst = sDst + r0;

    // GEMM2 weights register-resident (loop-invariant): 4 k-steps x 4 n-frags
    wmma::fragment<wmma::matrix_b, 16, 16, 16, __nv_bfloat16, wmma::row_major> w2f[4][4];
#pragma unroll
    for (int k = 0; k < 4; k++)
#pragma unroll
        for (int j = 0; j < 4; j++)
            wmma::load_matrix_sync(w2f[k][j], sW2h + (k * 16) * LDW_H + j * 16, LDW_H);

    for (int t = gw; t < nwt; t += gstride) {
        const int e0 = t * 32;

        // ---- gather: one lane per edge; f32 -> bf16, packed uint4 stores ----
        {
            const int e = e0 + lane;
            uint4* rp4 = reinterpret_cast<uint4*>(myInH + lane * LDIN_H);
            if (e < E) {
                const int s = srcp[e];
                const int d = dstp[e];
                myDst[lane] = d;
                const float4* xs = reinterpret_cast<const float4*>(x + (size_t)s * ND);
                const float4* xd = reinterpret_cast<const float4*>(x + (size_t)d * ND);
#pragma unroll
                for (int i = 0; i < 8; i++) {
                    float4 a = xs[2 * i], b = xs[2 * i + 1];
                    __nv_bfloat162 p0 = __floats2bfloat162_rn(a.x, a.y);
                    __nv_bfloat162 p1 = __floats2bfloat162_rn(a.z, a.w);
                    __nv_bfloat162 p2 = __floats2bfloat162_rn(b.x, b.y);
                    __nv_bfloat162 p3 = __floats2bfloat162_rn(b.z, b.w);
                    uint4 u;
                    u.x = *reinterpret_cast<unsigned*>(&p0);
                    u.y = *reinterpret_cast<unsigned*>(&p1);
                    u.z = *reinterpret_cast<unsigned*>(&p2);
                    u.w = *reinterpret_cast<unsigned*>(&p3);
                    rp4[i] = u;
                }
#pragma unroll
                for (int i = 0; i < 8; i++) {
                    float4 a = xd[2 * i], b = xd[2 * i + 1];
                    __nv_bfloat162 p0 = __floats2bfloat162_rn(a.x, a.y);
                    __nv_bfloat162 p1 = __floats2bfloat162_rn(a.z, a.w);
                    __nv_bfloat162 p2 = __floats2bfloat162_rn(b.x, b.y);
                    __nv_bfloat162 p3 = __floats2bfloat162_rn(b.z, b.w);
                    uint4 u;
                    u.x = *reinterpret_cast<unsigned*>(&p0);
                    u.y = *reinterpret_cast<unsigned*>(&p1);
                    u.z = *reinterpret_cast<unsigned*>(&p2);
                    u.w = *reinterpret_cast<unsigned*>(&p3);
                    rp4[8 + i] = u;
                }
                const float4* ap = reinterpret_cast<const float4*>(ea + (size_t)e * EDIM);
#pragma unroll
                for (int i = 0; i < 2; i++) {
                    float4 a = ap[2 * i], b = ap[2 * i + 1];
                    __nv_bfloat162 p0 = __floats2bfloat162_rn(a.x, a.y);
                    __nv_bfloat162 p1 = __floats2bfloat162_rn(a.z, a.w);
                    __nv_bfloat162 p2 = __floats2bfloat162_rn(b.x, b.y);
                    __nv_bfloat162 p3 = __floats2bfloat162_rn(b.z, b.w);
                    uint4 u;
                    u.x = *reinterpret_cast<unsigned*>(&p0);
                    u.y = *reinterpret_cast<unsigned*>(&p1);
                    u.z = *reinterpret_cast<unsigned*>(&p2);
                    u.w = *reinterpret_cast<unsigned*>(&p3);
                    rp4[16 + i] = u;
                }
            } else {
                uint4 z = make_uint4(0, 0, 0, 0);
#pragma unroll
                for (int i = 0; i < 18; i++) rp4[i] = z;
                myDst[lane] = 0;
            }
        }
        __syncwarp();

        // ---- GEMM1: (32 x 144) @ (144 x 64), b1 preloaded in C ----
        wmma::fragment<wmma::accumulator, 16, 16, 16, float> c[2][4];
        wmma::fragment<wmma::matrix_a, 16, 16, 16, __nv_bfloat16, wmma::row_major> af[2];
        wmma::fragment<wmma::matrix_b, 16, 16, 16, __nv_bfloat16, wmma::row_major> bf;
#pragma unroll
        for (int i = 0; i < 2; i++)
#pragma unroll
            for (int j = 0; j < 4; j++)
                wmma::load_matrix_sync(c[i][j], sB1T + j * 16, LDB_F, wmma::mem_row_major);
#pragma unroll
        for (int k = 0; k < MSGIN / 16; k++) {
            wmma::load_matrix_sync(af[0], myInH + k * 16, LDIN_H);
            wmma::load_matrix_sync(af[1], myInH + 16 * LDIN_H + k * 16, LDIN_H);
#pragma unroll
            for (int j = 0; j < 4; j++) {
                wmma::load_matrix_sync(bf, sW1h + (k * 16) * LDW_H + j * 16, LDW_H);
                wmma::mma_sync(c[0][j], af[0], bf, c[0][j]);
                wmma::mma_sync(c[1][j], af[1], bf, c[1][j]);
            }
        }
        // ReLU -> f32 scratch (aliases In; In is dead now)
#pragma unroll
        for (int i = 0; i < 2; i++)
#pragma unroll
            for (int j = 0; j < 4; j++) {
#pragma unroll
                for (int q = 0; q < c[i][j].num_elements; q++)
                    c[i][j].x[q] = fmaxf(c[i][j].x[q], 0.f);
                wmma::store_matrix_sync(myScr + (i * 16) * LDSC_F + j * 16, c[i][j],
                                        LDSC_F, wmma::mem_row_major);
            }
        __syncwarp();

        // convert scratch f32 -> bf16 H (one lane per row)
        {
            const float4* srow = reinterpret_cast<const float4*>(myScr + lane * LDSC_F);
            uint4* hrow = reinterpret_cast<uint4*>(myHh + lane * LDW_H);
#pragma unroll
            for (int i = 0; i < 8; i++) {
                float4 a = srow[2 * i], b = srow[2 * i + 1];
                __nv_bfloat162 p0 = __floats2bfloat162_rn(a.x, a.y);
                __nv_bfloat162 p1 = __floats2bfloat162_rn(a.z, a.w);
                __nv_bfloat162 p2 = __floats2bfloat162_rn(b.x, b.y);
                __nv_bfloat162 p3 = __floats2bfloat162_rn(b.z, b.w);
                uint4 u;
                u.x = *reinterpret_cast<unsigned*>(&p0);
                u.y = *reinterpret_cast<unsigned*>(&p1);
                u.z = *reinterpret_cast<unsigned*>(&p2);
                u.w = *reinterpret_cast<unsigned*>(&p3);
                hrow[i] = u;
            }
        }
        __syncwarp();

        // ---- GEMM2: (32 x 64) @ (64 x 64), weights in registers, C=0 ----
#pragma unroll
        for (int i = 0; i < 2; i++)
#pragma unroll
            for (int j = 0; j < 4; j++)
                wmma::fill_fragment(c[i][j], 0.f);
#pragma unroll
        for (int k = 0; k < HID / 16; k++) {
            wmma::load_matrix_sync(af[0], myHh + k * 16, LDW_H);
            wmma::load_matrix_sync(af[1], myHh + 16 * LDW_H + k * 16, LDW_H);
#pragma unroll
            for (int j = 0; j < 4; j++) {
                wmma::mma_sync(c[0][j], af[0], w2f[k][j], c[0][j]);
                wmma::mma_sync(c[1][j], af[1], w2f[k][j], c[1][j]);
            }
        }
        // messages (no bias; b2 folded into node kernel) -> scratch
#pragma unroll
        for (int i = 0; i < 2; i++)
#pragma unroll
            for (int j = 0; j < 4; j++)
                wmma::store_matrix_sync(myScr + (i * 16) * LDSC_F + j * 16, c[i][j],
                                        LDSC_F, wmma::mem_row_major);
        __syncwarp();

        // ---- scatter: 32 edges x 16 float4 atomics ----
#pragma unroll
        for (int i = 0; i < 16; i++) {
            const int idx = lane + 32 * i;     // 0..511
            const int el  = idx >> 4;
            const int c4  = idx & 15;
            const int e = e0 + el;
            if (e < E) {
                const int d = myDst[el];
                float4 v = *reinterpret_cast<const float4*>(myScr + el * LDSC_F + c4 * 4);
                atomicAdd(reinterpret_cast<float4*>(g_agg + (size_t)d * HID + c4 * 4), v);
            }
        }
        if (e0 + lane < E)
            atomicAdd(&g_cnt[myDst[lane]], 1.0f);
        __syncwarp();
    }
}

// ---------------------------------------------------------------------------
// Node kernel: fp32 exact. Mean + b2 folded into the aggregate during load:
//   agg_in = agg*inv + b2*(cnt*inv),  inv = 1/(cnt+1e-6)
// Then single-accumulator GEMM, r = acc + bu, out = x + relu(r).
// ---------------------------------------------------------------------------
#define FMA16(ACC, AV, BV)                                                    \
  ACC[0][0] = fmaf(AV.x, BV.x, ACC[0][0]);                                    \
  ACC[0][1] = fmaf(AV.x, BV.y, ACC[0][1]);                                    \
  ACC[0][2] = fmaf(AV.x, BV.z, ACC[0][2]);                                    \
  ACC[0][3] = fmaf(AV.x, BV.w, ACC[0][3]);                                    \
  ACC[1][0] = fmaf(AV.y, BV.x, ACC[1][0]);                                    \
  ACC[1][1] = fmaf(AV.y, BV.y, ACC[1][1]);                                    \
  ACC[1][2] = fmaf(AV.y, BV.z, ACC[1][2]);                                    \
  ACC[1][3] = fmaf(AV.y, BV.w, ACC[1][3]);                                    \
  ACC[2][0] = fmaf(AV.z, BV.x, ACC[2][0]);                                    \
  ACC[2][1] = fmaf(AV.z, BV.y, ACC[2][1]);                                    \
  ACC[2][2] = fmaf(AV.z, BV.z, ACC[2][2]);                                    \
  ACC[2][3] = fmaf(AV.z, BV.w, ACC[2][3]);                                    \
  ACC[3][0] = fmaf(AV.w, BV.x, ACC[3][0]);                                    \
  ACC[3][1] = fmaf(AV.w, BV.y, ACC[3][1]);                                    \
  ACC[3][2] = fmaf(AV.w, BV.z, ACC[3][2]);                                    \
  ACC[3][3] = fmaf(AV.w, BV.w, ACC[3][3]);

__global__ void __launch_bounds__(256, 3)
node_kernel(const float* __restrict__ x, const float* __restrict__ Wu,
            const float* __restrict__ bu, const float* __restrict__ b2,
            float* __restrict__ out, int N, int ntiles) {
    extern __shared__ float smn[];
    float* sWu = smn;                     // [128][64]
    float* sIn = sWu + 2 * ND * HID;      // [128][64]  (k-major, node minor)
    float* sBu = sIn + 2 * ND * TILE_N;   // [64]
    float* sB2 = sBu + HID;               // [64]

    const int tid = threadIdx.x;
    for (int i = tid; i < 2 * ND * HID; i += 256) sWu[i] = Wu[i];
    if (tid < HID) { sBu[tid] = bu[tid]; sB2[tid] = b2[tid]; }
    __syncthreads();

    const int tx = tid & 15;
    const int ty = tid >> 4;
    const int q  = tid & 3;
    const int ng = tid >> 2;

    for (int tile = blockIdx.x; tile < ntiles; tile += gridDim.x) {
        const int n0 = tile * TILE_N;
        {
            const int n = n0 + ng;
            if (n < N) {
                const float cnt = g_cnt[n];
                const float inv = 1.0f / (cnt + 1e-6f);
                const float f   = cnt * inv;
                const float4* xr = reinterpret_cast<const float4*>(x + (size_t)n * ND);
                const float4* ar = reinterpret_cast<const float4*>(g_agg + (size_t)n * HID);
#pragma unroll
                for (int i = 0; i < 4; i++) {
                    const int f4 = q + 4 * i;
                    const int k  = f4 * 4;
                    float4 v = xr[f4];
                    sIn[(k + 0) * TILE_N + ng] = v.x;
                    sIn[(k + 1) * TILE_N + ng] = v.y;
                    sIn[(k + 2) * TILE_N + ng] = v.z;
                    sIn[(k + 3) * TILE_N + ng] = v.w;
                    float4 w = ar[f4];
                    sIn[(ND + k + 0) * TILE_N + ng] = w.x * inv + sB2[k + 0] * f;
                    sIn[(ND + k + 1) * TILE_N + ng] = w.y * inv + sB2[k + 1] * f;
                    sIn[(ND + k + 2) * TILE_N + ng] = w.z * inv + sB2[k + 2] * f;
                    sIn[(ND + k + 3) * TILE_N + ng] = w.w * inv + sB2[k + 3] * f;
                }
            }
        }
        __syncthreads();

        float acc[4][4];
#pragma unroll
        for (int a = 0; a < 4; a++)
#pragma unroll
            for (int b = 0; b < 4; b++) acc[a][b] = 0.f;

#pragma unroll 8
        for (int k = 0; k < 2 * ND; k++) {
            float4 av = *reinterpret_cast<const float4*>(&sIn[k * TILE_N + tx * 4]);
            float4 bv = *reinterpret_cast<const float4*>(&sWu[k * HID + ty * 4]);
            FMA16(acc, av, bv)
        }

#pragma unroll
        for (int ei = 0; ei < 4; ei++) {
            const int n = n0 + tx * 4 + ei;
            if (n < N) {
                float4 o;
                float r;
                r = acc[ei][0] + sBu[ty * 4 + 0];
                o.x = sIn[(ty * 4 + 0) * TILE_N + tx * 4 + ei] + (r > 0.f ? r : 0.f);
                r = acc[ei][1] + sBu[ty * 4 + 1];
                o.y = sIn[(ty * 4 + 1) * TILE_N + tx * 4 + ei] + (r > 0.f ? r : 0.f);
                r = acc[ei][2] + sBu[ty * 4 + 2];
                o.z = sIn[(ty * 4 + 2) * TILE_N + tx * 4 + ei] + (r > 0.f ? r : 0.f);
                r = acc[ei][3] + sBu[ty * 4 + 3];
                o.w = sIn[(ty * 4 + 3) * TILE_N + tx * 4 + ei] + (r > 0.f ? r : 0.f);
                *reinterpret_cast<float4*>(out + (size_t)n * HID + ty * 4) = o;
            }
        }
        __syncthreads();
    }
}

// ---------------------------------------------------------------------------
extern "C" void kernel_launch(void* const* d_in, const int* in_sizes, int n_in,
                              void* d_out, int out_size) {
    const float* x   = (const float*)d_in[0];
    const int*   ei  = (const int*)d_in[1];
    const float* ea  = (const float*)d_in[2];
    const float* W1  = (const float*)d_in[3];
    const float* b1  = (const float*)d_in[4];
    const float* W2  = (const float*)d_in[5];
    const float* b2  = (const float*)d_in[6];
    const float* Wu  = (const float*)d_in[7];
    const float* bu  = (const float*)d_in[8];
    float* out = (float*)d_out;

    const int N = in_sizes[0] / ND;     // 100000
    const int E = in_sizes[2] / EDIM;   // 1600000

    const int smem_edge = (MSGIN * LDW_H + HID * LDW_H) * 2 + 16 * LDB_F * 4 +
                          256 * LDIN_H * 2 + 256 * LDW_H * 2 + 256 * 4;
    const int smem_node = (2 * ND * HID + 2 * ND * TILE_N + 2 * HID) * 4;

    cudaFuncSetAttribute(edge_kernel, cudaFuncAttributeMaxDynamicSharedMemorySize,
                         smem_edge);
    cudaFuncSetAttribute(node_kernel, cudaFuncAttributeMaxDynamicSharedMemorySize,
                         smem_node);

    const int nwt = (E + 31) / 32;                 // 32-edge warp tiles
    const int ntiles = (N + TILE_N - 1) / TILE_N;

    zero_kernel<<<2048, 256>>>(N);
    edge_kernel<<<148, 256, smem_edge>>>(x, ei, ea, W1, b1, W2, E, nwt);
    node_kernel<<<456, 256, smem_node>>>(x, Wu, bu, b2, out, N, ntiles);
}